// round 14
// baseline (speedup 1.0000x reference)
#include <cuda_runtime.h>
#include <cuda_bf16.h>
#include <cstdint>
#include <cstddef>

#define B_    64
#define L_    256
#define E_    300
#define H_    200
#define NH_   4
#define ENC_  400
#define DH_   100
#define GATE_ 800
#define XCOLS 1600
#define ROWS_ 16384
#define HS    68      // padded h stride (floats)
#define CL    5       // cluster size for lstm

typedef unsigned long long ull;

__device__ __forceinline__ ull pk2(float x, float y) {
    ull r; asm("mov.b64 %0,{%1,%2};" : "=l"(r) : "f"(x), "f"(y)); return r;
}
__device__ __forceinline__ void upk2(ull v, float& x, float& y) {
    asm("mov.b64 {%0,%1},%2;" : "=f"(x), "=f"(y) : "l"(v));
}
__device__ __forceinline__ ull ffma2(ull a, ull b, ull c) {
    ull d; asm("fma.rn.f32x2 %0,%1,%2,%3;" : "=l"(d) : "l"(a), "l"(b), "l"(c)); return d;
}
__device__ __forceinline__ ull fadd2(ull a, ull b) {
    ull d; asm("add.rn.f32x2 %0,%1,%2;" : "=l"(d) : "l"(a), "l"(b)); return d;
}
__device__ __forceinline__ uint32_t smem_u32(const void* p) {
    return (uint32_t)__cvta_generic_to_shared(p);
}
__device__ __forceinline__ void cpa16(uint32_t d, const void* s, bool v) {
    asm volatile("cp.async.cg.shared.global [%0], [%1], 16, %2;"
                 :: "r"(d), "l"(s), "r"(v ? 16 : 0));
}
__device__ __forceinline__ void cpa_commit() { asm volatile("cp.async.commit_group;"); }
template<int N> __device__ __forceinline__ void cpa_wait() {
    asm volatile("cp.async.wait_group %0;" :: "n"(N));
}
__device__ __forceinline__ void bulk_mc(uint32_t dst, const void* src, uint32_t bytes,
                                        uint32_t mbar, uint16_t mask) {
    asm volatile(
        "cp.async.bulk.shared::cluster.global.mbarrier::complete_tx::bytes.multicast::cluster"
        " [%0], [%1], %2, [%3], %4;"
        :: "r"(dst), "l"(src), "r"(bytes), "r"(mbar), "h"(mask) : "memory");
}
__device__ __forceinline__ void mbar_wait(uint32_t mbar, uint32_t parity) {
    asm volatile(
        "{\n\t"
        ".reg .pred P;\n\t"
        "WAIT_%=:\n\t"
        "mbarrier.try_wait.parity.acquire.cta.shared::cta.b64 P, [%0], %1, 0x989680;\n\t"
        "@!P bra WAIT_%=;\n\t"
        "}"
        :: "r"(mbar), "r"(parity) : "memory");
}
__device__ __forceinline__ unsigned ld_rlx(const unsigned* p) {
    unsigned v;
    asm volatile("ld.relaxed.gpu.global.u32 %0, [%1];" : "=r"(v) : "l"(p) : "memory");
    return v;
}

__device__ float g_xproj[(size_t)ROWS_ * XCOLS];
__device__ float g_h1[(size_t)ROWS_ * ENC_];
__device__ float g_KV[(size_t)ROWS_ * 800];
__device__ __align__(16) float g_hbuf[2][2][H_ * HS];   // [k][b], padded stride 68
__device__ float g_scores[B_ * NH_ * L_];
__device__ float g_p[B_ * NH_ * L_];
__device__ float g_pooled[B_ * ENC_];
__device__ float g_weff[ENC_];
__device__ int g_len[B_];
__device__ __align__(128) unsigned g_flags[128];  // dir0: [0..49], dir1: [64..113]
__device__ int g_mstride;

// ---- init ----
__global__ __launch_bounds__(512) void init_kernel(const unsigned char* __restrict__ mask,
                                                   const float* __restrict__ Wo,
                                                   const float* __restrict__ outW) {
    int tid = threadIdx.x;
    int ms = (mask[1] == 0) ? 4 : 1;  // bool vs int32 mask
    if (tid == 0) g_mstride = ms;
    if (tid < 128) g_flags[tid] = 0u;
    for (int i = tid; i < 2 * 2 * H_ * HS; i += blockDim.x) (&g_hbuf[0][0][0])[i] = 0.f;
    if (tid < B_) {
        int s = 0;
        for (int t = 0; t < L_; t++) s += (mask[(size_t)(tid * L_ + t) * ms] != 0) ? 1 : 0;
        g_len[tid] = s;
    }
    int warp = tid >> 5, lane = tid & 31;
    for (int i = warp; i < ENC_; i += 16) {
        float s = 0.f;
        for (int j = lane; j < ENC_; j += 32) s += Wo[i * ENC_ + j] * outW[j];
#pragma unroll
        for (int o = 16; o; o >>= 1) s += __shfl_xor_sync(0xffffffffu, s, o);
        if (lane == 0) g_weff[i] = s;
    }
}

__device__ __forceinline__ bool mk(const unsigned char* m, int idx) {
    return m[(size_t)idx * g_mstride] != 0;
}
__device__ __forceinline__ float sigm(float x) { return 1.f / (1.f + expf(-x)); }

__device__ __forceinline__ float4 ld4g(const float* p, int k, int lim) {
    if (k + 3 < lim) return *(const float4*)(p + k);
    float4 v;
    v.x = (k + 0 < lim) ? p[k + 0] : 0.f;
    v.y = (k + 1 < lim) ? p[k + 1] : 0.f;
    v.z = (k + 2 < lim) ? p[k + 2] : 0.f;
    v.w = (k + 3 < lim) ? p[k + 3] : 0.f;
    return v;
}

// ---- GEMM1: xproj = embed_W[x] @ [Wi_f|Wi_b] + bias, KTILE=16 pipelined ----
__global__ __launch_bounds__(256) void gemm_xproj_kernel(
    const int* __restrict__ x, const float* __restrict__ embW,
    const float* __restrict__ Wif, const float* __restrict__ Wib,
    const float* __restrict__ bf, const float* __restrict__ bb) {
    __shared__ float As[2][16][132];
    __shared__ float Bs[2][16][132];
    __shared__ int tok[128];
    const int NT = 19;
    int bn = blockIdx.x * 128, bm = blockIdx.y * 128;
    int tid = threadIdx.x, tx = tid & 15, ty = tid >> 4;
    if (tid < 128) tok[tid] = x[bm + tid];
    __syncthreads();
    ull acc2[8][4];
#pragma unroll
    for (int i = 0; i < 8; i++)
#pragma unroll
        for (int j = 0; j < 4; j++) acc2[i][j] = 0ULL;
    int ar = tid >> 1, akb = (tid & 1) * 8;
    int bk = tid >> 5, bcb = (tid & 31) * 4;
    const float* arow = embW + (size_t)tok[ar] * E_;
    int bcol = bn + bcb;
    bool bcok = (bcol + 3) < XCOLS;
    const float* bsrcf = Wif + bcol;
    const float* bsrcb = Wib + (bcol - GATE_);

    float4 a0R, a1R, a0N, a1N;
    {
        a0R = ld4g(arow, akb, E_);
        a1R = ld4g(arow, akb + 4, E_);
        const float* base = (bcol < GATE_) ? bsrcf : bsrcb;
        cpa16(smem_u32(&Bs[0][bk][bcb]),     base + (size_t)bk * GATE_,       bcok && (bk < E_));
        cpa16(smem_u32(&Bs[0][bk + 8][bcb]), base + (size_t)(bk + 8) * GATE_, bcok && (bk + 8 < E_));
        cpa_commit();
    }
    for (int it = 0; it < NT; ++it) {
        int buf = it & 1;
        As[buf][akb + 0][ar] = a0R.x; As[buf][akb + 1][ar] = a0R.y;
        As[buf][akb + 2][ar] = a0R.z; As[buf][akb + 3][ar] = a0R.w;
        As[buf][akb + 4][ar] = a1R.x; As[buf][akb + 5][ar] = a1R.y;
        As[buf][akb + 6][ar] = a1R.z; As[buf][akb + 7][ar] = a1R.w;
        if (it + 1 < NT) {
            int k0 = (it + 1) * 16;
            a0N = ld4g(arow, k0 + akb, E_);
            a1N = ld4g(arow, k0 + akb + 4, E_);
            const float* base = (bcol < GATE_) ? bsrcf : bsrcb;
            int kb0 = k0 + bk, kb1 = k0 + bk + 8;
            cpa16(smem_u32(&Bs[buf ^ 1][bk][bcb]),     base + (size_t)kb0 * GATE_, bcok && (kb0 < E_));
            cpa16(smem_u32(&Bs[buf ^ 1][bk + 8][bcb]), base + (size_t)kb1 * GATE_, bcok && (kb1 < E_));
            cpa_commit();
            cpa_wait<1>();
        } else {
            cpa_wait<0>();
        }
        __syncthreads();
#pragma unroll
        for (int k = 0; k < 16; k++) {
            float4 a0 = *(const float4*)&As[buf][k][ty * 8];
            float4 a1 = *(const float4*)&As[buf][k][ty * 8 + 4];
            float4 b0 = *(const float4*)&Bs[buf][k][tx * 8];
            float4 b1 = *(const float4*)&Bs[buf][k][tx * 8 + 4];
            float a[8] = {a0.x, a0.y, a0.z, a0.w, a1.x, a1.y, a1.z, a1.w};
            ull bb2[4] = {pk2(b0.x, b0.y), pk2(b0.z, b0.w), pk2(b1.x, b1.y), pk2(b1.z, b1.w)};
#pragma unroll
            for (int i = 0; i < 8; i++) {
                ull ad = pk2(a[i], a[i]);
#pragma unroll
                for (int j = 0; j < 4; j++) acc2[i][j] = ffma2(ad, bb2[j], acc2[i][j]);
            }
        }
        __syncthreads();
        a0R = a0N; a1R = a1N;
    }
#pragma unroll
    for (int i = 0; i < 8; i++) {
        int r = bm + ty * 8 + i;
#pragma unroll
        for (int j = 0; j < 4; j++) {
            float v0, v1; upk2(acc2[i][j], v0, v1);
            int c = bn + tx * 8 + 2 * j;
            if (c < XCOLS) {
                float bias = (c < GATE_) ? bf[c] : bb[c - GATE_];
                g_xproj[(size_t)r * XCOLS + c] = v0 + bias;
            }
            if (c + 1 < XCOLS) {
                float bias = (c + 1 < GATE_) ? bf[c + 1] : bb[c + 1 - GATE_];
                g_xproj[(size_t)r * XCOLS + c + 1] = v1 + bias;
            }
        }
    }
}

// ---- persistent biLSTM: multicast h exchange + atomic-free flag barrier ----
__global__ __launch_bounds__(256, 1) __cluster_dims__(CL, 1, 1)
void lstm_kernel(const float* __restrict__ Whf, const float* __restrict__ Whb) {
    extern __shared__ float h_s[];  // [200][68] floats = 54400 B
    __shared__ __align__(8) unsigned long long mbar_s;
    int blk = blockIdx.x, dir = blk / 50, slice = blk % 50;
    int u0 = slice * 4;
    const float* Wh = dir ? Whb : Whf;
    int tid = threadIdx.x, lane = tid & 31, warp = tid >> 5;
    int ksub = lane & 7, uu = lane >> 3, ucol = u0 + uu;
    int bmine = warp * 8 + ksub;
    int mylen = g_len[bmine];
    uint32_t mbar = smem_u32(&mbar_s);
    uint32_t hsb = smem_u32(h_s);
    uint32_t rank;
    asm("mov.u32 %0, %%cluster_ctarank;" : "=r"(rank));
    unsigned* flags = &g_flags[dir * 64];

    if (tid == 0)
        asm volatile("mbarrier.init.shared.b64 [%0], 1;" :: "r"(mbar) : "memory");
    asm volatile("barrier.cluster.arrive.aligned;" ::: "memory");
    asm volatile("barrier.cluster.wait.aligned;" ::: "memory");

    float w[25][4];
#pragma unroll
    for (int kk = 0; kk < 25; kk++)
#pragma unroll
        for (int g = 0; g < 4; g++)
            w[kk][g] = Wh[(ksub * 25 + kk) * GATE_ + g * H_ + ucol];

    float c = 0.f;
    float xg[4];
    {
        int t0 = dir ? (L_ - 1) : 0;
        const float* xp = g_xproj + (size_t)(bmine * L_ + t0) * XCOLS + dir * GATE_ + ucol;
#pragma unroll
        for (int g = 0; g < 4; g++) xg[g] = __ldg(&xp[g * H_]);
    }

    const uint32_t SLICE_B = (H_ * HS * 4) / CL;  // 10880 bytes
    const uint32_t SLICE_F = (H_ * HS) / CL;      // 2720 floats

    // prologue: issue multicast fetch of h0 (init_kernel completion ordered it)
    if (tid == 0) {
        asm volatile("mbarrier.arrive.expect_tx.shared.b64 _, [%0], %1;"
                     :: "r"(mbar), "r"((uint32_t)(H_ * HS * 4)) : "memory");
        bulk_mc(hsb + rank * SLICE_B, &g_hbuf[0][dir][rank * SLICE_F],
                SLICE_B, mbar, (uint16_t)0x1F);
    }

    for (int step = 0; step < L_; step++) {
        int t = dir ? (L_ - 1 - step) : step;
        int wb = (step & 1) ^ 1;
        mbar_wait(mbar, (uint32_t)(step & 1));

        ull acc[4][4];
#pragma unroll
        for (int bp = 0; bp < 4; bp++)
#pragma unroll
            for (int g = 0; g < 4; g++) acc[bp][g] = 0ULL;

#pragma unroll
        for (int kk = 0; kk < 25; kk++) {
            int k = ksub * 25 + kk;
            const float* hrow = &h_s[k * HS + warp * 8];
            ull hp[4];
#pragma unroll
            for (int bp = 0; bp < 4; bp++) hp[bp] = *(const ull*)(hrow + 2 * bp);
#pragma unroll
            for (int g = 0; g < 4; g++) {
                ull wd = pk2(w[kk][g], w[kk][g]);
#pragma unroll
                for (int bp = 0; bp < 4; bp++) acc[bp][g] = ffma2(hp[bp], wd, acc[bp][g]);
            }
        }
#pragma unroll
        for (int bp = 0; bp < 4; bp++)
#pragma unroll
            for (int g = 0; g < 4; g++) {
                ull v = acc[bp][g];
                v = fadd2(v, __shfl_xor_sync(0xffffffffu, v, 1));
                v = fadd2(v, __shfl_xor_sync(0xffffffffu, v, 2));
                v = fadd2(v, __shfl_xor_sync(0xffffffffu, v, 4));
                acc[bp][g] = v;
            }
        float hout;
        {
            int mybp = ksub >> 1;
            bool odd = ksub & 1;
            float gv[4];
#pragma unroll
            for (int g = 0; g < 4; g++) {
                float lo, hi; upk2(acc[mybp][g], lo, hi);
                gv[g] = (odd ? hi : lo) + xg[g];
            }
            float cn = sigm(gv[1]) * c + sigm(gv[0]) * tanhf(gv[2]);
            float hn = sigm(gv[3]) * tanhf(cn);
            bool m = (t < mylen);
            hout = m ? hn : h_s[ucol * HS + bmine];
            if (m) c = cn;
            g_hbuf[wb][dir][ucol * HS + bmine] = hout;
        }
        __syncthreads();
        // arrival: own flag, release (no atomics, no contention)
        if (tid == 0)
            asm volatile("st.release.gpu.global.u32 [%0], %1;"
                         :: "l"(&flags[slice]), "r"((unsigned)(step + 1)) : "memory");
        // off critical path
        g_h1[(size_t)(bmine * L_ + t) * ENC_ + dir * H_ + ucol] = hout;
        if (step + 1 < L_) {
            int tn = dir ? (L_ - 2 - step) : (step + 1);
            const float* xp = g_xproj + (size_t)(bmine * L_ + tn) * XCOLS + dir * GATE_ + ucol;
#pragma unroll
            for (int g = 0; g < 4; g++) xg[g] = __ldg(&xp[g * H_]);
        }
        // warp 0: poll all 50 flags (coalesced), then issue next fetch.
        // warps 1-7 fall straight through to the next mbar_wait.
        if (warp == 0 && step + 1 < L_) {
            unsigned tgt = (unsigned)(step + 1);
            if (lane < 25) {
                while (ld_rlx(&flags[2 * lane]) < tgt) {}
                while (ld_rlx(&flags[2 * lane + 1]) < tgt) {}
            }
            __syncwarp();
            if (lane == 0) {
                asm volatile("mbarrier.arrive.expect_tx.shared.b64 _, [%0], %1;"
                             :: "r"(mbar), "r"((uint32_t)(H_ * HS * 4)) : "memory");
                bulk_mc(hsb + rank * SLICE_B, &g_hbuf[wb][dir][rank * SLICE_F],
                        SLICE_B, mbar, (uint16_t)0x1F);
            }
        }
    }
    asm volatile("barrier.cluster.arrive.aligned;" ::: "memory");
    asm volatile("barrier.cluster.wait.aligned;" ::: "memory");
}

// ---- GEMM2: KV = h1 @ [Wk|Wv], KTILE=16 pipelined ----
__global__ __launch_bounds__(256) void gemm_kv_kernel(
    const float* __restrict__ Wk, const float* __restrict__ Wv) {
    __shared__ float As[2][16][132];
    __shared__ float Bs[2][16][132];
    const int NT = 25;
    int bn = blockIdx.x * 128, bm = blockIdx.y * 128;
    int tid = threadIdx.x, tx = tid & 15, ty = tid >> 4;
    ull acc2[8][4];
#pragma unroll
    for (int i = 0; i < 8; i++)
#pragma unroll
        for (int j = 0; j < 4; j++) acc2[i][j] = 0ULL;
    int ar = tid >> 1, akb = (tid & 1) * 8;
    int bk = tid >> 5, bcb = (tid & 31) * 4;
    const float* arow = g_h1 + (size_t)(bm + ar) * ENC_;
    int bcol = bn + bcb;
    bool bcok = (bcol + 3) < 800;
    const float* bsrc = (bcol < ENC_) ? (Wk + bcol) : (Wv + (bcol - ENC_));

    float4 a0R, a1R, a0N, a1N;
    {
        a0R = *(const float4*)(arow + akb);
        a1R = *(const float4*)(arow + akb + 4);
        cpa16(smem_u32(&Bs[0][bk][bcb]),     bsrc + (size_t)bk * ENC_,       bcok);
        cpa16(smem_u32(&Bs[0][bk + 8][bcb]), bsrc + (size_t)(bk + 8) * ENC_, bcok);
        cpa_commit();
    }
    for (int it = 0; it < NT; ++it) {
        int buf = it & 1;
        As[buf][akb + 0][ar] = a0R.x; As[buf][akb + 1][ar] = a0R.y;
        As[buf][akb + 2][ar] = a0R.z; As[buf][akb + 3][ar] = a0R.w;
        As[buf][akb + 4][ar] = a1R.x; As[buf][akb + 5][ar] = a1R.y;
        As[buf][akb + 6][ar] = a1R.z; As[buf][akb + 7][ar] = a1R.w;
        if (it + 1 < NT) {
            int k0 = (it + 1) * 16;
            a0N = *(const float4*)(arow + k0 + akb);
            a1N = *(const float4*)(arow + k0 + akb + 4);
            cpa16(smem_u32(&Bs[buf ^ 1][bk][bcb]),     bsrc + (size_t)(k0 + bk) * ENC_,     bcok);
            cpa16(smem_u32(&Bs[buf ^ 1][bk + 8][bcb]), bsrc + (size_t)(k0 + bk + 8) * ENC_, bcok);
            cpa_commit();
            cpa_wait<1>();
        } else {
            cpa_wait<0>();
        }
        __syncthreads();
#pragma unroll
        for (int k = 0; k < 16; k++) {
            float4 a0 = *(const float4*)&As[buf][k][ty * 8];
            float4 a1 = *(const float4*)&As[buf][k][ty * 8 + 4];
            float4 b0 = *(const float4*)&Bs[buf][k][tx * 8];
            float4 b1 = *(const float4*)&Bs[buf][k][tx * 8 + 4];
            float a[8] = {a0.x, a0.y, a0.z, a0.w, a1.x, a1.y, a1.z, a1.w};
            ull bb2[4] = {pk2(b0.x, b0.y), pk2(b0.z, b0.w), pk2(b1.x, b1.y), pk2(b1.z, b1.w)};
#pragma unroll
            for (int i = 0; i < 8; i++) {
                ull ad = pk2(a[i], a[i]);
#pragma unroll
                for (int j = 0; j < 4; j++) acc2[i][j] = ffma2(ad, bb2[j], acc2[i][j]);
            }
        }
        __syncthreads();
        a0R = a0N; a1R = a1N;
    }
#pragma unroll
    for (int i = 0; i < 8; i++) {
        int r = bm + ty * 8 + i;
#pragma unroll
        for (int j = 0; j < 4; j++) {
            float v0, v1; upk2(acc2[i][j], v0, v1);
            int cix = bn + tx * 8 + 2 * j;
            if (cix < 800) g_KV[(size_t)r * 800 + cix] = v0;
            if (cix + 1 < 800) g_KV[(size_t)r * 800 + cix + 1] = v1;
        }
    }
}

// ---- scores ----
__global__ __launch_bounds__(256) void scores_kernel(const float* __restrict__ q) {
    __shared__ float qs[ENC_];
    int tid = threadIdx.x;
    for (int i = tid; i < ENC_; i += 256) qs[i] = q[i];
    __syncthreads();
    int warp = tid >> 5, lane = tid & 31;
    int row = blockIdx.x * 8 + warp;
    const float* kr = g_KV + (size_t)row * 800;
    int b = row >> 8, l = row & 255;
#pragma unroll
    for (int h = 0; h < NH_; h++) {
        float a = 0.f;
        for (int d = lane; d < DH_; d += 32) a += qs[h * DH_ + d] * kr[h * DH_ + d];
#pragma unroll
        for (int o = 16; o; o >>= 1) a += __shfl_xor_sync(0xffffffffu, a, o);
        if (lane == 0) g_scores[((b * NH_ + h) << 8) + l] = 1000.0f * a;
    }
}

__device__ __forceinline__ float bsum(float v, float* red) {
#pragma unroll
    for (int o = 16; o; o >>= 1) v += __shfl_xor_sync(0xffffffffu, v, o);
    int lane = threadIdx.x & 31, warp = threadIdx.x >> 5;
    __syncthreads();
    if (lane == 0) red[warp] = v;
    __syncthreads();
    float r = red[0];
#pragma unroll
    for (int i = 1; i < 8; i++) r += red[i];
    return r;
}
__device__ __forceinline__ float bmax(float v, float* red) {
#pragma unroll
    for (int o = 16; o; o >>= 1) v = fmaxf(v, __shfl_xor_sync(0xffffffffu, v, o));
    int lane = threadIdx.x & 31, warp = threadIdx.x >> 5;
    __syncthreads();
    if (lane == 0) red[warp] = v;
    __syncthreads();
    float r = red[0];
#pragma unroll
    for (int i = 1; i < 8; i++) r = fmaxf(r, red[i]);
    return r;
}

// ---- budget projection ----
__global__ __launch_bounds__(256) void budget_kernel(const unsigned char* __restrict__ mask) {
    __shared__ float red[8];
    int b = blockIdx.x, h = blockIdx.y, l = threadIdx.x;
    bool m = mk(mask, b * L_ + l);
    float s = m ? g_scores[((b * NH_ + h) << 8) + l] : -1e9f;
    float len = bsum(m ? 1.f : 0.f, red);
    float budget = roundf(0.2f * len);
    float p0 = fminf(fmaxf(s, 0.f), 1.f);
    bool need = bsum(p0, red) > budget;
    float hi = bmax(m ? s : 0.f, red) + 1.f;
    float lo = 0.f;
    for (int it = 0; it < 60; it++) {
        float mid = 0.5f * (lo + hi);
        float val = bsum(fminf(fmaxf(s - mid, 0.f), 1.f), red);
        if (val > budget) lo = mid; else hi = mid;
    }
    float tau0 = 0.5f * (lo + hi);
    float r = s - tau0;
    bool fr = (r > 0.f) && (r < 1.f) && m;
    bool h1f = (r >= 1.f) && m;
    float nfree = bsum(fr ? 1.f : 0.f, red);
    float sfree = bsum(fr ? s : 0.f, red);
    float nhi = bsum(h1f ? 1.f : 0.f, red);
    float tau = (sfree + nhi - budget) / fmaxf(nfree, 1.f);
    tau = (nfree > 0.f) ? tau : tau0;
    float pv = fminf(fmaxf(s - tau, 0.f), 1.f);
    g_p[((b * NH_ + h) << 8) + l] = need ? pv : p0;
}

// ---- zp ----
__global__ void zp_kernel(const unsigned char* __restrict__ mask, float* __restrict__ out) {
    int b = blockIdx.x, l = threadIdx.x;
    float v = 0.f;
    if (mk(mask, b * L_ + l))
        v = 0.25f * (g_p[((b * NH_) << 8) + l] + g_p[((b * NH_ + 1) << 8) + l] +
                     g_p[((b * NH_ + 2) << 8) + l] + g_p[((b * NH_ + 3) << 8) + l]);
    out[B_ + b * L_ + l] = v;
}

// ---- pooled ----
__global__ __launch_bounds__(128) void pooled_kernel() {
    __shared__ float ps[L_];
    int b = blockIdx.x, h = blockIdx.y, d = threadIdx.x;
    for (int i = d; i < L_; i += 128) ps[i] = g_p[((b * NH_ + h) << 8) + i];
    __syncthreads();
    if (d >= DH_) return;
    const float* vb = g_KV + (size_t)(b * L_) * 800 + ENC_ + h * DH_ + d;
    float a0 = 0.f, a1 = 0.f, a2 = 0.f, a3 = 0.f;
#pragma unroll 4
    for (int l = 0; l < L_; l += 4) {
        a0 += ps[l] * vb[(size_t)l * 800];
        a1 += ps[l + 1] * vb[(size_t)(l + 1) * 800];
        a2 += ps[l + 2] * vb[(size_t)(l + 2) * 800];
        a3 += ps[l + 3] * vb[(size_t)(l + 3) * 800];
    }
    g_pooled[b * ENC_ + h * DH_ + d] = (a0 + a1) + (a2 + a3);
}

// ---- y ----
__global__ __launch_bounds__(128) void final_kernel(const float* __restrict__ outb,
                                                    float* __restrict__ out) {
    __shared__ float red[4];
    int b = blockIdx.x, tid = threadIdx.x;
    float v = 0.f;
    for (int i = tid; i < ENC_; i += 128) v += g_pooled[b * ENC_ + i] * g_weff[i];
#pragma unroll
    for (int o = 16; o; o >>= 1) v += __shfl_xor_sync(0xffffffffu, v, o);
    if ((tid & 31) == 0) red[tid >> 5] = v;
    __syncthreads();
    if (tid == 0) out[b] = sigm(red[0] + red[1] + red[2] + red[3] + outb[0]);
}

extern "C" void kernel_launch(void* const* d_in, const int* in_sizes, int n_in,
                              void* d_out, int out_size) {
    const int* x = (const int*)d_in[0];
    const unsigned char* mask = (const unsigned char*)d_in[2];
    const float* embW = (const float*)d_in[3];
    const float* Wif = (const float*)d_in[4];
    const float* Whf = (const float*)d_in[5];
    const float* bf = (const float*)d_in[6];
    const float* Wib = (const float*)d_in[7];
    const float* Whb = (const float*)d_in[8];
    const float* bb = (const float*)d_in[9];
    const float* Wk = (const float*)d_in[10];
    const float* Wv = (const float*)d_in[11];
    const float* q = (const float*)d_in[12];
    const float* Wo = (const float*)d_in[13];
    const float* outW = (const float*)d_in[14];
    const float* outb = (const float*)d_in[15];
    float* out = (float*)d_out;

    const int lstm_smem = H_ * HS * (int)sizeof(float);  // 54400 B
    static bool attr_set = false;
    if (!attr_set) {
        cudaFuncSetAttribute(lstm_kernel, cudaFuncAttributeMaxDynamicSharedMemorySize,
                             lstm_smem);
        attr_set = true;
    }

    init_kernel<<<1, 512>>>(mask, Wo, outW);
    gemm_xproj_kernel<<<dim3(13, 128), 256>>>(x, embW, Wif, Wib, bf, bb);
    lstm_kernel<<<100, 256, lstm_smem>>>(Whf, Whb);
    gemm_kv_kernel<<<dim3(7, 128), 256>>>(Wk, Wv);
    scores_kernel<<<ROWS_ / 8, 256>>>(q);
    budget_kernel<<<dim3(B_, NH_), 256>>>(mask);
    zp_kernel<<<B_, L_>>>(mask, out);
    pooled_kernel<<<dim3(B_, NH_), 128>>>();
    final_kernel<<<B_, 128>>>(outb, out);
}

// round 15
// speedup vs baseline: 1.3644x; 1.3644x over previous
#include <cuda_runtime.h>
#include <cuda_bf16.h>
#include <cstdint>
#include <cstddef>

#define B_    64
#define L_    256
#define E_    300
#define H_    200
#define NH_   4
#define ENC_  400
#define DH_   100
#define GATE_ 800
#define XCOLS 1600
#define ROWS_ 16384
#define HS    68      // padded h stride (floats)
#define CL    5       // cluster size for lstm

typedef unsigned long long ull;

__device__ __forceinline__ ull pk2(float x, float y) {
    ull r; asm("mov.b64 %0,{%1,%2};" : "=l"(r) : "f"(x), "f"(y)); return r;
}
__device__ __forceinline__ void upk2(ull v, float& x, float& y) {
    asm("mov.b64 {%0,%1},%2;" : "=f"(x), "=f"(y) : "l"(v));
}
__device__ __forceinline__ ull ffma2(ull a, ull b, ull c) {
    ull d; asm("fma.rn.f32x2 %0,%1,%2,%3;" : "=l"(d) : "l"(a), "l"(b), "l"(c)); return d;
}
__device__ __forceinline__ ull fadd2(ull a, ull b) {
    ull d; asm("add.rn.f32x2 %0,%1,%2;" : "=l"(d) : "l"(a), "l"(b)); return d;
}
__device__ __forceinline__ uint32_t smem_u32(const void* p) {
    return (uint32_t)__cvta_generic_to_shared(p);
}
__device__ __forceinline__ void cpa16(uint32_t d, const void* s, bool v) {
    asm volatile("cp.async.cg.shared.global [%0], [%1], 16, %2;"
                 :: "r"(d), "l"(s), "r"(v ? 16 : 0));
}
__device__ __forceinline__ void cpa_commit() { asm volatile("cp.async.commit_group;"); }
template<int N> __device__ __forceinline__ void cpa_wait() {
    asm volatile("cp.async.wait_group %0;" :: "n"(N));
}
__device__ __forceinline__ void bulk_mc(uint32_t dst, const void* src, uint32_t bytes,
                                        uint32_t mbar, uint16_t mask) {
    asm volatile(
        "cp.async.bulk.shared::cluster.global.mbarrier::complete_tx::bytes.multicast::cluster"
        " [%0], [%1], %2, [%3], %4;"
        :: "r"(dst), "l"(src), "r"(bytes), "r"(mbar), "h"(mask) : "memory");
}
__device__ __forceinline__ void mbar_wait(uint32_t mbar, uint32_t parity) {
    asm volatile(
        "{\n\t"
        ".reg .pred P;\n\t"
        "WAIT_%=:\n\t"
        "mbarrier.try_wait.parity.acquire.cta.shared::cta.b64 P, [%0], %1, 0x989680;\n\t"
        "@!P bra WAIT_%=;\n\t"
        "}"
        :: "r"(mbar), "r"(parity) : "memory");
}

__device__ float g_xproj[(size_t)ROWS_ * XCOLS];
__device__ float g_h1[(size_t)ROWS_ * ENC_];
__device__ float g_KV[(size_t)ROWS_ * 800];
__device__ __align__(16) float g_hbuf[2][2][H_ * HS];   // [k][b], padded stride 68
__device__ float g_p[B_ * NH_ * L_];
__device__ float g_pooled[B_ * ENC_];
__device__ float g_weff[ENC_];
__device__ int g_len[B_];
__device__ unsigned g_bar2[2];
__device__ int g_mstride;

// ---- init ----
__global__ __launch_bounds__(512) void init_kernel(const unsigned char* __restrict__ mask,
                                                   const float* __restrict__ Wo,
                                                   const float* __restrict__ outW) {
    int tid = threadIdx.x;
    int ms = (mask[1] == 0) ? 4 : 1;  // bool vs int32 mask
    if (tid == 0) {
        g_bar2[0] = 0u; g_bar2[1] = 0u;
        g_mstride = ms;
    }
    for (int i = tid; i < 2 * 2 * H_ * HS; i += blockDim.x) (&g_hbuf[0][0][0])[i] = 0.f;
    if (tid < B_) {
        int s = 0;
        for (int t = 0; t < L_; t++) s += (mask[(size_t)(tid * L_ + t) * ms] != 0) ? 1 : 0;
        g_len[tid] = s;
    }
    int warp = tid >> 5, lane = tid & 31;
    for (int i = warp; i < ENC_; i += 16) {
        float s = 0.f;
        for (int j = lane; j < ENC_; j += 32) s += Wo[i * ENC_ + j] * outW[j];
#pragma unroll
        for (int o = 16; o; o >>= 1) s += __shfl_xor_sync(0xffffffffu, s, o);
        if (lane == 0) g_weff[i] = s;
    }
}

__device__ __forceinline__ bool mk(const unsigned char* m, int idx) {
    return m[(size_t)idx * g_mstride] != 0;
}
__device__ __forceinline__ float sigm(float x) { return 1.f / (1.f + expf(-x)); }

__device__ __forceinline__ float4 ld4g(const float* p, int k, int lim) {
    if (k + 3 < lim) return *(const float4*)(p + k);
    float4 v;
    v.x = (k + 0 < lim) ? p[k + 0] : 0.f;
    v.y = (k + 1 < lim) ? p[k + 1] : 0.f;
    v.z = (k + 2 < lim) ? p[k + 2] : 0.f;
    v.w = (k + 3 < lim) ? p[k + 3] : 0.f;
    return v;
}

// ---- GEMM1: xproj = embed_W[x] @ [Wi_f|Wi_b] + bias, KTILE=16 pipelined ----
__global__ __launch_bounds__(256) void gemm_xproj_kernel(
    const int* __restrict__ x, const float* __restrict__ embW,
    const float* __restrict__ Wif, const float* __restrict__ Wib,
    const float* __restrict__ bf, const float* __restrict__ bb) {
    __shared__ float As[2][16][132];
    __shared__ float Bs[2][16][132];
    __shared__ int tok[128];
    const int NT = 19;
    int bn = blockIdx.x * 128, bm = blockIdx.y * 128;
    int tid = threadIdx.x, tx = tid & 15, ty = tid >> 4;
    if (tid < 128) tok[tid] = x[bm + tid];
    __syncthreads();
    ull acc2[8][4];
#pragma unroll
    for (int i = 0; i < 8; i++)
#pragma unroll
        for (int j = 0; j < 4; j++) acc2[i][j] = 0ULL;
    int ar = tid >> 1, akb = (tid & 1) * 8;
    int bk = tid >> 5, bcb = (tid & 31) * 4;
    const float* arow = embW + (size_t)tok[ar] * E_;
    int bcol = bn + bcb;
    bool bcok = (bcol + 3) < XCOLS;
    const float* bsrcf = Wif + bcol;
    const float* bsrcb = Wib + (bcol - GATE_);

    float4 a0R, a1R, a0N, a1N;
    {
        a0R = ld4g(arow, akb, E_);
        a1R = ld4g(arow, akb + 4, E_);
        const float* base = (bcol < GATE_) ? bsrcf : bsrcb;
        cpa16(smem_u32(&Bs[0][bk][bcb]),     base + (size_t)bk * GATE_,       bcok && (bk < E_));
        cpa16(smem_u32(&Bs[0][bk + 8][bcb]), base + (size_t)(bk + 8) * GATE_, bcok && (bk + 8 < E_));
        cpa_commit();
    }
    for (int it = 0; it < NT; ++it) {
        int buf = it & 1;
        As[buf][akb + 0][ar] = a0R.x; As[buf][akb + 1][ar] = a0R.y;
        As[buf][akb + 2][ar] = a0R.z; As[buf][akb + 3][ar] = a0R.w;
        As[buf][akb + 4][ar] = a1R.x; As[buf][akb + 5][ar] = a1R.y;
        As[buf][akb + 6][ar] = a1R.z; As[buf][akb + 7][ar] = a1R.w;
        if (it + 1 < NT) {
            int k0 = (it + 1) * 16;
            a0N = ld4g(arow, k0 + akb, E_);
            a1N = ld4g(arow, k0 + akb + 4, E_);
            const float* base = (bcol < GATE_) ? bsrcf : bsrcb;
            int kb0 = k0 + bk, kb1 = k0 + bk + 8;
            cpa16(smem_u32(&Bs[buf ^ 1][bk][bcb]),     base + (size_t)kb0 * GATE_, bcok && (kb0 < E_));
            cpa16(smem_u32(&Bs[buf ^ 1][bk + 8][bcb]), base + (size_t)kb1 * GATE_, bcok && (kb1 < E_));
            cpa_commit();
            cpa_wait<1>();
        } else {
            cpa_wait<0>();
        }
        __syncthreads();
#pragma unroll
        for (int k = 0; k < 16; k++) {
            float4 a0 = *(const float4*)&As[buf][k][ty * 8];
            float4 a1 = *(const float4*)&As[buf][k][ty * 8 + 4];
            float4 b0 = *(const float4*)&Bs[buf][k][tx * 8];
            float4 b1 = *(const float4*)&Bs[buf][k][tx * 8 + 4];
            float a[8] = {a0.x, a0.y, a0.z, a0.w, a1.x, a1.y, a1.z, a1.w};
            ull bb2[4] = {pk2(b0.x, b0.y), pk2(b0.z, b0.w), pk2(b1.x, b1.y), pk2(b1.z, b1.w)};
#pragma unroll
            for (int i = 0; i < 8; i++) {
                ull ad = pk2(a[i], a[i]);
#pragma unroll
                for (int j = 0; j < 4; j++) acc2[i][j] = ffma2(ad, bb2[j], acc2[i][j]);
            }
        }
        __syncthreads();
        a0R = a0N; a1R = a1N;
    }
#pragma unroll
    for (int i = 0; i < 8; i++) {
        int r = bm + ty * 8 + i;
#pragma unroll
        for (int j = 0; j < 4; j++) {
            float v0, v1; upk2(acc2[i][j], v0, v1);
            int c = bn + tx * 8 + 2 * j;
            if (c < XCOLS) {
                float bias = (c < GATE_) ? bf[c] : bb[c - GATE_];
                g_xproj[(size_t)r * XCOLS + c] = v0 + bias;
            }
            if (c + 1 < XCOLS) {
                float bias = (c + 1 < GATE_) ? bf[c + 1] : bb[c + 1 - GATE_];
                g_xproj[(size_t)r * XCOLS + c + 1] = v1 + bias;
            }
        }
    }
}

// ---- persistent biLSTM: R13 config (multicast + red.release + tid0 poll) ----
__global__ __launch_bounds__(256, 1) __cluster_dims__(CL, 1, 1)
void lstm_kernel(const float* __restrict__ Whf, const float* __restrict__ Whb) {
    extern __shared__ float h_s[];  // [200][68] floats = 54400 B
    __shared__ __align__(8) unsigned long long mbar_s;
    int blk = blockIdx.x, dir = blk / 50, slice = blk % 50;
    int u0 = slice * 4;
    const float* Wh = dir ? Whb : Whf;
    unsigned* bar = &g_bar2[dir];
    int tid = threadIdx.x, lane = tid & 31, warp = tid >> 5;
    int ksub = lane & 7, uu = lane >> 3, ucol = u0 + uu;
    int bmine = warp * 8 + ksub;
    int mylen = g_len[bmine];
    uint32_t mbar = smem_u32(&mbar_s);
    uint32_t hsb = smem_u32(h_s);
    uint32_t rank;
    asm("mov.u32 %0, %%cluster_ctarank;" : "=r"(rank));

    if (tid == 0)
        asm volatile("mbarrier.init.shared.b64 [%0], 1;" :: "r"(mbar) : "memory");
    asm volatile("barrier.cluster.arrive.aligned;" ::: "memory");
    asm volatile("barrier.cluster.wait.aligned;" ::: "memory");

    float w[25][4];
#pragma unroll
    for (int kk = 0; kk < 25; kk++)
#pragma unroll
        for (int g = 0; g < 4; g++)
            w[kk][g] = Wh[(ksub * 25 + kk) * GATE_ + g * H_ + ucol];

    float c = 0.f;
    float xg[4];
    {
        int t0 = dir ? (L_ - 1) : 0;
        const float* xp = g_xproj + (size_t)(bmine * L_ + t0) * XCOLS + dir * GATE_ + ucol;
#pragma unroll
        for (int g = 0; g < 4; g++) xg[g] = __ldg(&xp[g * H_]);
    }

    const uint32_t SLICE_B = (H_ * HS * 4) / CL;  // 10880 bytes
    const uint32_t SLICE_F = (H_ * HS) / CL;      // 2720 floats

    for (int step = 0; step < L_; step++) {
        int t = dir ? (L_ - 1 - step) : step;
        int rb = step & 1, wb = rb ^ 1;
        if (tid == 0) {
            asm volatile("mbarrier.arrive.expect_tx.shared.b64 _, [%0], %1;"
                         :: "r"(mbar), "r"((uint32_t)(H_ * HS * 4)) : "memory");
            bulk_mc(hsb + rank * SLICE_B, &g_hbuf[rb][dir][rank * SLICE_F],
                    SLICE_B, mbar, (uint16_t)0x1F);
        }
        mbar_wait(mbar, (uint32_t)(step & 1));

        ull acc[4][4];
#pragma unroll
        for (int bp = 0; bp < 4; bp++)
#pragma unroll
            for (int g = 0; g < 4; g++) acc[bp][g] = 0ULL;

#pragma unroll
        for (int kk = 0; kk < 25; kk++) {
            int k = ksub * 25 + kk;
            const float* hrow = &h_s[k * HS + warp * 8];
            ull hp[4];
#pragma unroll
            for (int bp = 0; bp < 4; bp++) hp[bp] = *(const ull*)(hrow + 2 * bp);
#pragma unroll
            for (int g = 0; g < 4; g++) {
                ull wd = pk2(w[kk][g], w[kk][g]);
#pragma unroll
                for (int bp = 0; bp < 4; bp++) acc[bp][g] = ffma2(hp[bp], wd, acc[bp][g]);
            }
        }
#pragma unroll
        for (int bp = 0; bp < 4; bp++)
#pragma unroll
            for (int g = 0; g < 4; g++) {
                ull v = acc[bp][g];
                v = fadd2(v, __shfl_xor_sync(0xffffffffu, v, 1));
                v = fadd2(v, __shfl_xor_sync(0xffffffffu, v, 2));
                v = fadd2(v, __shfl_xor_sync(0xffffffffu, v, 4));
                acc[bp][g] = v;
            }
        float hout;
        {
            int mybp = ksub >> 1;
            bool odd = ksub & 1;
            float gv[4];
#pragma unroll
            for (int g = 0; g < 4; g++) {
                float lo, hi; upk2(acc[mybp][g], lo, hi);
                gv[g] = (odd ? hi : lo) + xg[g];
            }
            float cn = sigm(gv[1]) * c + sigm(gv[0]) * tanhf(gv[2]);
            float hn = sigm(gv[3]) * tanhf(cn);
            bool m = (t < mylen);
            hout = m ? hn : h_s[ucol * HS + bmine];
            if (m) c = cn;
            g_hbuf[wb][dir][ucol * HS + bmine] = hout;
        }
        __syncthreads();
        if (tid == 0)
            asm volatile("red.release.gpu.global.add.u32 [%0], %1;"
                         :: "l"(bar), "r"(1u) : "memory");
        // off critical path: h1 store + next x-gate prefetch
        g_h1[(size_t)(bmine * L_ + t) * ENC_ + dir * H_ + ucol] = hout;
        if (step + 1 < L_) {
            int tn = dir ? (L_ - 2 - step) : (step + 1);
            const float* xp = g_xproj + (size_t)(bmine * L_ + tn) * XCOLS + dir * GATE_ + ucol;
#pragma unroll
            for (int g = 0; g < 4; g++) xg[g] = __ldg(&xp[g * H_]);
        }
        if (tid == 0) {
            unsigned tgt = (unsigned)(step + 1) * 50u;
            unsigned v;
            do {
                asm volatile("ld.relaxed.gpu.global.u32 %0, [%1];"
                             : "=r"(v) : "l"(bar) : "memory");
            } while (v < tgt);
        }
    }
    asm volatile("barrier.cluster.arrive.aligned;" ::: "memory");
    asm volatile("barrier.cluster.wait.aligned;" ::: "memory");
}

// ---- GEMM2: KV = h1 @ [Wk|Wv], KTILE=16 pipelined ----
__global__ __launch_bounds__(256) void gemm_kv_kernel(
    const float* __restrict__ Wk, const float* __restrict__ Wv) {
    __shared__ float As[2][16][132];
    __shared__ float Bs[2][16][132];
    const int NT = 25;
    int bn = blockIdx.x * 128, bm = blockIdx.y * 128;
    int tid = threadIdx.x, tx = tid & 15, ty = tid >> 4;
    ull acc2[8][4];
#pragma unroll
    for (int i = 0; i < 8; i++)
#pragma unroll
        for (int j = 0; j < 4; j++) acc2[i][j] = 0ULL;
    int ar = tid >> 1, akb = (tid & 1) * 8;
    int bk = tid >> 5, bcb = (tid & 31) * 4;
    const float* arow = g_h1 + (size_t)(bm + ar) * ENC_;
    int bcol = bn + bcb;
    bool bcok = (bcol + 3) < 800;
    const float* bsrc = (bcol < ENC_) ? (Wk + bcol) : (Wv + (bcol - ENC_));

    float4 a0R, a1R, a0N, a1N;
    {
        a0R = *(const float4*)(arow + akb);
        a1R = *(const float4*)(arow + akb + 4);
        cpa16(smem_u32(&Bs[0][bk][bcb]),     bsrc + (size_t)bk * ENC_,       bcok);
        cpa16(smem_u32(&Bs[0][bk + 8][bcb]), bsrc + (size_t)(bk + 8) * ENC_, bcok);
        cpa_commit();
    }
    for (int it = 0; it < NT; ++it) {
        int buf = it & 1;
        As[buf][akb + 0][ar] = a0R.x; As[buf][akb + 1][ar] = a0R.y;
        As[buf][akb + 2][ar] = a0R.z; As[buf][akb + 3][ar] = a0R.w;
        As[buf][akb + 4][ar] = a1R.x; As[buf][akb + 5][ar] = a1R.y;
        As[buf][akb + 6][ar] = a1R.z; As[buf][akb + 7][ar] = a1R.w;
        if (it + 1 < NT) {
            int k0 = (it + 1) * 16;
            a0N = *(const float4*)(arow + k0 + akb);
            a1N = *(const float4*)(arow + k0 + akb + 4);
            cpa16(smem_u32(&Bs[buf ^ 1][bk][bcb]),     bsrc + (size_t)(k0 + bk) * ENC_,     bcok);
            cpa16(smem_u32(&Bs[buf ^ 1][bk + 8][bcb]), bsrc + (size_t)(k0 + bk + 8) * ENC_, bcok);
            cpa_commit();
            cpa_wait<1>();
        } else {
            cpa_wait<0>();
        }
        __syncthreads();
#pragma unroll
        for (int k = 0; k < 16; k++) {
            float4 a0 = *(const float4*)&As[buf][k][ty * 8];
            float4 a1 = *(const float4*)&As[buf][k][ty * 8 + 4];
            float4 b0 = *(const float4*)&Bs[buf][k][tx * 8];
            float4 b1 = *(const float4*)&Bs[buf][k][tx * 8 + 4];
            float a[8] = {a0.x, a0.y, a0.z, a0.w, a1.x, a1.y, a1.z, a1.w};
            ull bb2[4] = {pk2(b0.x, b0.y), pk2(b0.z, b0.w), pk2(b1.x, b1.y), pk2(b1.z, b1.w)};
#pragma unroll
            for (int i = 0; i < 8; i++) {
                ull ad = pk2(a[i], a[i]);
#pragma unroll
                for (int j = 0; j < 4; j++) acc2[i][j] = ffma2(ad, bb2[j], acc2[i][j]);
            }
        }
        __syncthreads();
        a0R = a0N; a1R = a1N;
    }
#pragma unroll
    for (int i = 0; i < 8; i++) {
        int r = bm + ty * 8 + i;
#pragma unroll
        for (int j = 0; j < 4; j++) {
            float v0, v1; upk2(acc2[i][j], v0, v1);
            int cix = bn + tx * 8 + 2 * j;
            if (cix < 800) g_KV[(size_t)r * 800 + cix] = v0;
            if (cix + 1 < 800) g_KV[(size_t)r * 800 + cix + 1] = v1;
        }
    }
}

__device__ __forceinline__ float bsum(float v, float* red) {
#pragma unroll
    for (int o = 16; o; o >>= 1) v += __shfl_xor_sync(0xffffffffu, v, o);
    int lane = threadIdx.x & 31, warp = threadIdx.x >> 5;
    __syncthreads();
    if (lane == 0) red[warp] = v;
    __syncthreads();
    float r = red[0];
#pragma unroll
    for (int i = 1; i < 8; i++) r += red[i];
    return r;
}
__device__ __forceinline__ float bmax(float v, float* red) {
#pragma unroll
    for (int o = 16; o; o >>= 1) v = fmaxf(v, __shfl_xor_sync(0xffffffffu, v, o));
    int lane = threadIdx.x & 31, warp = threadIdx.x >> 5;
    __syncthreads();
    if (lane == 0) red[warp] = v;
    __syncthreads();
    float r = red[0];
#pragma unroll
    for (int i = 1; i < 8; i++) r = fmaxf(r, red[i]);
    return r;
}

// ---- budget projection with fused score computation, block per (b,h) ----
__global__ __launch_bounds__(256) void budget_kernel(const float* __restrict__ q,
                                                     const unsigned char* __restrict__ mask) {
    __shared__ float red[8];
    __shared__ float qs[DH_];
    int b = blockIdx.x, h = blockIdx.y, l = threadIdx.x;
    if (l < DH_) qs[l] = q[h * DH_ + l];
    __syncthreads();

    // fused score: s_raw = 1000 * q[h]·K[b,l,h,:]
    const float4* kr = (const float4*)(g_KV + (size_t)(b * L_ + l) * 800 + h * DH_);
    const float4* q4 = (const float4*)qs;
    float a0 = 0.f, a1 = 0.f;
#pragma unroll
    for (int i = 0; i < 25; i += 2) {
        float4 v = kr[i], qv = q4[i];
        a0 += v.x * qv.x + v.y * qv.y + v.z * qv.z + v.w * qv.w;
        if (i + 1 < 25) {
            float4 v2 = kr[i + 1], qv2 = q4[i + 1];
            a1 += v2.x * qv2.x + v2.y * qv2.y + v2.z * qv2.z + v2.w * qv2.w;
        }
    }
    float s_raw = 1000.0f * (a0 + a1);

    bool m = mk(mask, b * L_ + l);
    float s = m ? s_raw : -1e9f;
    float budget = roundf(0.2f * (float)g_len[b]);
    float p0 = fminf(fmaxf(s, 0.f), 1.f);
    bool need = bsum(p0, red) > budget;
    float hi = bmax(m ? s : 0.f, red) + 1.f;
    float lo = 0.f;
    for (int it = 0; it < 60; it++) {
        float mid = 0.5f * (lo + hi);
        float val = bsum(fminf(fmaxf(s - mid, 0.f), 1.f), red);
        if (val > budget) lo = mid; else hi = mid;
    }
    float tau0 = 0.5f * (lo + hi);
    float r = s - tau0;
    bool fr = (r > 0.f) && (r < 1.f) && m;
    bool h1f = (r >= 1.f) && m;
    float nfree = bsum(fr ? 1.f : 0.f, red);
    float sfree = bsum(fr ? s : 0.f, red);
    float nhi = bsum(h1f ? 1.f : 0.f, red);
    float tau = (sfree + nhi - budget) / fmaxf(nfree, 1.f);
    tau = (nfree > 0.f) ? tau : tau0;
    float pv = fminf(fmaxf(s - tau, 0.f), 1.f);
    g_p[((b * NH_ + h) << 8) + l] = need ? pv : p0;
}

// ---- zp ----
__global__ void zp_kernel(const unsigned char* __restrict__ mask, float* __restrict__ out) {
    int b = blockIdx.x, l = threadIdx.x;
    float v = 0.f;
    if (mk(mask, b * L_ + l))
        v = 0.25f * (g_p[((b * NH_) << 8) + l] + g_p[((b * NH_ + 1) << 8) + l] +
                     g_p[((b * NH_ + 2) << 8) + l] + g_p[((b * NH_ + 3) << 8) + l]);
    out[B_ + b * L_ + l] = v;
}

// ---- pooled ----
__global__ __launch_bounds__(128) void pooled_kernel() {
    __shared__ float ps[L_];
    int b = blockIdx.x, h = blockIdx.y, d = threadIdx.x;
    for (int i = d; i < L_; i += 128) ps[i] = g_p[((b * NH_ + h) << 8) + i];
    __syncthreads();
    if (d >= DH_) return;
    const float* vb = g_KV + (size_t)(b * L_) * 800 + ENC_ + h * DH_ + d;
    float a0 = 0.f, a1 = 0.f, a2 = 0.f, a3 = 0.f;
#pragma unroll 4
    for (int l = 0; l < L_; l += 4) {
        a0 += ps[l] * vb[(size_t)l * 800];
        a1 += ps[l + 1] * vb[(size_t)(l + 1) * 800];
        a2 += ps[l + 2] * vb[(size_t)(l + 2) * 800];
        a3 += ps[l + 3] * vb[(size_t)(l + 3) * 800];
    }
    g_pooled[b * ENC_ + h * DH_ + d] = (a0 + a1) + (a2 + a3);
}

// ---- y ----
__global__ __launch_bounds__(128) void final_kernel(const float* __restrict__ outb,
                                                    float* __restrict__ out) {
    __shared__ float red[4];
    int b = blockIdx.x, tid = threadIdx.x;
    float v = 0.f;
    for (int i = tid; i < ENC_; i += 128) v += g_pooled[b * ENC_ + i] * g_weff[i];
#pragma unroll
    for (int o = 16; o; o >>= 1) v += __shfl_xor_sync(0xffffffffu, v, o);
    if ((tid & 31) == 0) red[tid >> 5] = v;
    __syncthreads();
    if (tid == 0) out[b] = sigm(red[0] + red[1] + red[2] + red[3] + outb[0]);
}

extern "C" void kernel_launch(void* const* d_in, const int* in_sizes, int n_in,
                              void* d_out, int out_size) {
    const int* x = (const int*)d_in[0];
    const unsigned char* mask = (const unsigned char*)d_in[2];
    const float* embW = (const float*)d_in[3];
    const float* Wif = (const float*)d_in[4];
    const float* Whf = (const float*)d_in[5];
    const float* bf = (const float*)d_in[6];
    const float* Wib = (const float*)d_in[7];
    const float* Whb = (const float*)d_in[8];
    const float* bb = (const float*)d_in[9];
    const float* Wk = (const float*)d_in[10];
    const float* Wv = (const float*)d_in[11];
    const float* q = (const float*)d_in[12];
    const float* Wo = (const float*)d_in[13];
    const float* outW = (const float*)d_in[14];
    const float* outb = (const float*)d_in[15];
    float* out = (float*)d_out;

    const int lstm_smem = H_ * HS * (int)sizeof(float);  // 54400 B
    static bool attr_set = false;
    if (!attr_set) {
        cudaFuncSetAttribute(lstm_kernel, cudaFuncAttributeMaxDynamicSharedMemorySize,
                             lstm_smem);
        attr_set = true;
    }

    init_kernel<<<1, 512>>>(mask, Wo, outW);
    gemm_xproj_kernel<<<dim3(13, 128), 256>>>(x, embW, Wif, Wib, bf, bb);
    lstm_kernel<<<100, 256, lstm_smem>>>(Whf, Whb);
    gemm_kv_kernel<<<dim3(7, 128), 256>>>(Wk, Wv);
    budget_kernel<<<dim3(B_, NH_), 256>>>(q, mask);
    zp_kernel<<<B_, L_>>>(mask, out);
    pooled_kernel<<<dim3(B_, NH_), 128>>>();
    final_kernel<<<B_, 128>>>(outb, out);
}